// round 9
// baseline (speedup 1.0000x reference)
#include <cuda_runtime.h>
#include <cstdint>

#define NB   2
#define NS   2048
#define ND   2048
#define NH   16
#define NDH  128
#define NTOK (NB * NS)

// Scratch (device globals: no allocation allowed in kernel_launch)
__device__ float g_Q  [(size_t)NTOK * ND];      // roped Q (tf32, col-interleaved)
__device__ float g_O  [(size_t)NTOK * ND];      // attention out (tf32, col-interleaved)
__device__ float g_KV [(size_t)NTOK * 2 * NDH]; // KV projection result
__device__ float g_Kr [(size_t)NTOK * NDH];     // roped K (tf32, col-interleaved)
__device__ float g_Vt [(size_t)NDH * NTOK];     // V^T (tf32), key dim pair-interleaved
__device__ float g_xr [(size_t)NTOK * ND];      // x  (tf32, plain)
__device__ float g_wqr[(size_t)ND * ND];        // wq (tf32, plain)
__device__ float g_wor[(size_t)ND * ND];        // wo (tf32, col-interleaved)
__device__ float g_wkvT[(size_t)256 * ND];      // wkv^T (tf32, plain)

// ===========================================================================
// Helpers
// ===========================================================================
__device__ __forceinline__ uint32_t smem_u32(const void* p) {
  uint32_t a;
  asm("{ .reg .u64 t; cvta.to.shared.u64 t, %1; cvt.u32.u64 %0, t; }"
      : "=r"(a) : "l"(p));
  return a;
}
__device__ __forceinline__ void cp_async16(uint32_t dst, const void* src) {
  asm volatile("cp.async.cg.shared.global [%0], [%1], 16;" ::"r"(dst), "l"(src));
}
#define CP_ASYNC_COMMIT() asm volatile("cp.async.commit_group;" ::: "memory")
template <int N>
__device__ __forceinline__ void cp_async_wait() {
  asm volatile("cp.async.wait_group %0;" ::"n"(N) : "memory");
}
__device__ __forceinline__ uint32_t f2tf32(float x) {
  uint32_t r;
  asm("cvt.rna.tf32.f32 %0, %1;" : "=r"(r) : "f"(x));
  return r;
}
__device__ __forceinline__ float f2tf32f(float x) {
  return __uint_as_float(f2tf32(x));
}
__device__ __forceinline__ void mma_tf32(float* c, const uint32_t* a,
                                         const uint32_t* b) {
  asm volatile(
      "mma.sync.aligned.m16n8k8.row.col.f32.tf32.tf32.f32 "
      "{%0,%1,%2,%3}, {%4,%5,%6,%7}, {%8,%9}, {%0,%1,%2,%3};"
      : "+f"(c[0]), "+f"(c[1]), "+f"(c[2]), "+f"(c[3])
      : "r"(a[0]), "r"(a[1]), "r"(a[2]), "r"(a[3]), "r"(b[0]), "r"(b[1]));
}
// Pair interleave within each 8-group: fragment pair (c, c+4) -> adjacent.
__device__ __forceinline__ int colmap8(int c) {
  int r = c & 7;
  return (c & ~7) | ((r < 4) ? (r << 1) : (((r - 4) << 1) | 1));
}
// Inverse: word slot w -> original index.
__device__ __forceinline__ int invmap8(int w) {
  int r = w & 7;
  return (w & ~7) | ((r & 1) ? ((r >> 1) + 4) : (r >> 1));
}

// ===========================================================================
// tf32 mma.sync GEMM: C[M,N] = A[M,K] @ B[N,K]^T. Operands PRE-ROUNDED tf32.
// Tile 128x128x32, 256 threads, 3 stages, single barrier per chunk.
// ===========================================================================
#define TBM 128
#define TBN 128
#define TBK 32
#define TSTRIDE 36
#define TILE_FLOATS (TBM * TSTRIDE)
#define STAGE_FLOATS (2 * TILE_FLOATS)
#define TSTAGES 3
#define MMA_SMEM (TSTAGES * STAGE_FLOATS * 4)

__global__ void __launch_bounds__(256, 2)
tf32_mma_gemm(const float* __restrict__ A, const float* __restrict__ B,
              float* __restrict__ C, int M, int N, int K) {
  extern __shared__ float sm[];
  const uint32_t* smu = (const uint32_t*)sm;
  const int tid = threadIdx.x;
  const int wid = tid >> 5;
  const int lane = tid & 31;
  const int gid = lane >> 2;
  const int tg = lane & 3;
  const int wm = wid & 1;
  const int wn = wid >> 1;
  const int bm = blockIdx.y * TBM;
  const int bn = blockIdx.x * TBN;
  const int nchunks = K / TBK;

  const float* gA = A + (size_t)bm * K;
  const float* gB = B + (size_t)bn * K;
  const uint32_t sbase = smem_u32(sm);

  auto load_chunk = [&](int c) {
    const int s = c % TSTAGES;
    const uint32_t sa = sbase + s * STAGE_FLOATS * 4;
    const uint32_t sbb = sa + TILE_FLOATS * 4;
    const int k0 = c * TBK;
#pragma unroll
    for (int i = 0; i < 4; i++) {
      int idx = tid + i * 256;
      int r = idx >> 3, c4 = idx & 7;
      cp_async16(sa + (r * TSTRIDE + c4 * 4) * 4, gA + (size_t)r * K + k0 + c4 * 4);
    }
#pragma unroll
    for (int i = 0; i < 4; i++) {
      int idx = tid + i * 256;
      int r = idx >> 3, c4 = idx & 7;
      cp_async16(sbb + (r * TSTRIDE + c4 * 4) * 4, gB + (size_t)r * K + k0 + c4 * 4);
    }
    CP_ASYNC_COMMIT();
  };

  float acc[4][4][4];
#pragma unroll
  for (int mf = 0; mf < 4; mf++)
#pragma unroll
    for (int nf = 0; nf < 4; nf++)
#pragma unroll
      for (int r = 0; r < 4; r++) acc[mf][nf][r] = 0.f;

  load_chunk(0);
  load_chunk(1);

  for (int i = 0; i < nchunks; i++) {
    if (i < nchunks - 1)
      cp_async_wait<1>();
    else
      cp_async_wait<0>();
    __syncthreads();
    // Single barrier per chunk: stage (i+2)%3's previous readers (iter i-1)
    // are guaranteed past by the sync above.
    if (i + 2 < nchunks) load_chunk(i + 2);

    const uint32_t* As = smu + (i % TSTAGES) * STAGE_FLOATS;
    const uint32_t* Bs = As + TILE_FLOATS;

#pragma unroll
    for (int k8 = 0; k8 < 4; k8++) {
      uint32_t a[4][4], b[4][2];
#pragma unroll
      for (int mf = 0; mf < 4; mf++) {
        const uint32_t* ap = As + (wm * 64 + mf * 16 + gid) * TSTRIDE + k8 * 8 + tg;
        a[mf][0] = ap[0];
        a[mf][1] = ap[8 * TSTRIDE];
        a[mf][2] = ap[4];
        a[mf][3] = ap[8 * TSTRIDE + 4];
      }
#pragma unroll
      for (int nf = 0; nf < 4; nf++) {
        const uint32_t* bp = Bs + (wn * 32 + nf * 8 + gid) * TSTRIDE + k8 * 8 + tg;
        b[nf][0] = bp[0];
        b[nf][1] = bp[4];
      }
#pragma unroll
      for (int mf = 0; mf < 4; mf++)
#pragma unroll
        for (int nf = 0; nf < 4; nf++) mma_tf32(acc[mf][nf], a[mf], b[nf]);
    }
  }

#pragma unroll
  for (int mf = 0; mf < 4; mf++) {
    int row0 = bm + wm * 64 + mf * 16 + gid;
#pragma unroll
    for (int nf = 0; nf < 4; nf++) {
      int col = bn + wn * 32 + nf * 8 + 2 * tg;
      *(float2*)(C + (size_t)row0 * N + col) =
          make_float2(acc[mf][nf][0], acc[mf][nf][1]);
      *(float2*)(C + (size_t)(row0 + 8) * N + col) =
          make_float2(acc[mf][nf][2], acc[mf][nf][3]);
    }
  }
}

// ---------------------------------------------------------------------------
// Elementwise tf32 rounding; interleaved variant for wo.
// ---------------------------------------------------------------------------
__global__ void round_tf32_kernel(const float* __restrict__ in,
                                  float* __restrict__ out, int n4) {
  int i = blockIdx.x * 256 + threadIdx.x;
  if (i < n4) {
    float4 v = ((const float4*)in)[i];
    v.x = f2tf32f(v.x);
    v.y = f2tf32f(v.y);
    v.z = f2tf32f(v.z);
    v.w = f2tf32f(v.w);
    ((float4*)out)[i] = v;
  }
}

__global__ void round_tf32_ilv_kernel(const float* __restrict__ in,
                                      float* __restrict__ out, int n4) {
  int i = blockIdx.x * 256 + threadIdx.x;
  if (i < n4) {
    float4 v = ((const float4*)in)[i];
    int c = i * 4;
    out[colmap8(c + 0)] = f2tf32f(v.x);
    out[colmap8(c + 1)] = f2tf32f(v.y);
    out[colmap8(c + 2)] = f2tf32f(v.z);
    out[colmap8(c + 3)] = f2tf32f(v.w);
  }
}

// ---------------------------------------------------------------------------
// Transpose + round: wkv [2048][256] -> wkvT [256][2048] (tf32).
// ---------------------------------------------------------------------------
__global__ void transpose_round_kernel(const float* __restrict__ in,
                                       float* __restrict__ out) {
  __shared__ float t[32][33];
  const int k0 = blockIdx.x * 32;
  const int n0 = blockIdx.y * 32;
  const int tx = threadIdx.x;
  const int ty = threadIdx.y;
#pragma unroll
  for (int j = 0; j < 4; j++)
    t[ty + 8 * j][tx] = in[(size_t)(k0 + ty + 8 * j) * 256 + n0 + tx];
  __syncthreads();
#pragma unroll
  for (int j = 0; j < 4; j++)
    out[(size_t)(n0 + ty + 8 * j) * 2048 + k0 + tx] = f2tf32f(t[tx][ty + 8 * j]);
}

// ---------------------------------------------------------------------------
// V transpose: g_KV[tok][128+d] -> g_Vt[d][keyslot], keys pair-interleaved
// within 8-groups (key s stored at word colmap8(s)), tf32-rounded.
// ---------------------------------------------------------------------------
__global__ void transpose_v_kernel(const float* __restrict__ KV,
                                   float* __restrict__ Vt) {
  __shared__ float t[32][33];
  const int tok0 = blockIdx.x * 32;
  const int d0 = blockIdx.y * 32;
  const int tx = threadIdx.x;
  const int ty = threadIdx.y;
#pragma unroll
  for (int j = 0; j < 4; j++)
    t[ty + 8 * j][tx] = KV[(size_t)(tok0 + ty + 8 * j) * 256 + 128 + d0 + tx];
  __syncthreads();
#pragma unroll
  for (int j = 0; j < 4; j++) {
    int s = invmap8(tx);  // word slot tx holds key invmap8(tx)
    Vt[(size_t)(d0 + ty + 8 * j) * NTOK + tok0 + tx] = f2tf32f(t[s][ty + 8 * j]);
  }
}

// ---------------------------------------------------------------------------
// RoPE on Q, in-place, tf32-rounded + col-interleaved (per head).
// ---------------------------------------------------------------------------
__global__ void rope_q_kernel(float* __restrict__ Q, const int* __restrict__ past) {
  const int tok = blockIdx.x;
  const int s = tok % NS;
  const int pos = past[0] + s;
  const int t = threadIdx.x;
  const int h = t >> 6;
  const int i = t & 63;
  float fr = 1.0f / powf(10000.0f, (float)(2 * i) / 128.0f);
  float ang = (float)pos * fr;
  float sn, cs;
  sincosf(ang, &sn, &cs);
  float* q = Q + (size_t)tok * ND + h * NDH;
  float x1 = q[i];
  float x2 = q[i + 64];
  __syncthreads();  // in-place permuted writes: all reads first
  int ci = colmap8(i);
  q[ci]      = f2tf32f(x1 * cs - x2 * sn);
  q[ci + 64] = f2tf32f(x2 * cs + x1 * sn);
}

// ---------------------------------------------------------------------------
// Split KV: exact K/V outputs; Kr (roped, tf32, interleaved).
// ---------------------------------------------------------------------------
__global__ void split_rope_k_kernel(const float* __restrict__ KV,
                                    float* __restrict__ Kout,
                                    float* __restrict__ Vout,
                                    float* __restrict__ Kr) {
  const int tok = blockIdx.x;
  const int s = tok % NS;
  const int t = threadIdx.x;
  const float* kv = KV + (size_t)tok * 256;
  Kout[(size_t)tok * NDH + t] = kv[t];
  Vout[(size_t)tok * NDH + t] = kv[128 + t];
  if (t < 64) {
    float fr = 1.0f / powf(10000.0f, (float)(2 * t) / 128.0f);
    float ang = (float)s * fr;
    float sn, cs;
    sincosf(ang, &sn, &cs);
    float x1 = kv[t];
    float x2 = kv[t + 64];
    int ct = colmap8(t);
    Kr[(size_t)tok * NDH + ct]      = f2tf32f(x1 * cs - x2 * sn);
    Kr[(size_t)tok * NDH + ct + 64] = f2tf32f(x2 * cs + x1 * sn);
  }
}

// ===========================================================================
// Tensor-core flash attention, tf32 mma.sync, pipelined K/V double buffer.
// Q/K col-interleaved and V^T key-interleaved -> all fragment loads LDS.64.
// Smem (words): qs[128][136] | ks[2][64][136] | vt[2][128][72]
// ===========================================================================
#define AQ_STR 136
#define AVT_STR 72
#define QS_OFF 0
#define KS_OFF (128 * AQ_STR)                    // 17408
#define KS_SZ (64 * AQ_STR)                      // 8704
#define VT_OFF (KS_OFF + 2 * KS_SZ)              // 34816
#define VT_SZ (128 * AVT_STR)                    // 9216
#define ATTN_SMEM ((VT_OFF + 2 * VT_SZ) * 4)     // 212992 bytes

__global__ void __launch_bounds__(256, 1) attn_mma_kernel(
    const float* __restrict__ Q, const float* __restrict__ Kr,
    const float* __restrict__ Vt, float* __restrict__ O,
    const int* __restrict__ past) {
  extern __shared__ float sm[];
  uint32_t* smu = (uint32_t*)sm;
  const uint32_t sbase = smem_u32(sm);

  const int qt = (int)gridDim.x - 1 - (int)blockIdx.x;  // heavy tiles first
  const int h = blockIdx.y;
  const int b = blockIdx.z;
  const int tid = threadIdx.x;
  const int w = tid >> 5;
  const int lane = tid & 31;
  const int gid = lane >> 2;
  const int tg = lane & 3;
  const int q0 = qt * 128;
  const int pl = past[0];
  const float scale = 0.08838834764831845f;  // 1/sqrt(128)
  const int nkt = 2 * qt + 2;

  auto load_tile = [&](int kt) {
    const int s = kt & 1;
    const uint32_t ksb = sbase + (KS_OFF + s * KS_SZ) * 4;
    const uint32_t vtb = sbase + (VT_OFF + s * VT_SZ) * 4;
    const size_t tok0 = (size_t)(b * NS) + kt * 64;
#pragma unroll
    for (int i = 0; i < 8; i++) {
      int idx = tid + i * 256;
      int r = idx >> 5, c4 = idx & 31;
      cp_async16(ksb + (r * AQ_STR + c4 * 4) * 4, Kr + (tok0 + r) * NDH + c4 * 4);
    }
    // V^T tile: 128 dh-rows x 64 keys (key slots pre-interleaved in gmem)
#pragma unroll
    for (int i = 0; i < 8; i++) {
      int idx = tid + i * 256;
      int r = idx >> 4, c4 = idx & 15;  // dh row r, 16B chunk c4
      cp_async16(vtb + (r * AVT_STR + c4 * 4) * 4,
                 Vt + (size_t)r * NTOK + tok0 + c4 * 4);
    }
    CP_ASYNC_COMMIT();
  };

  // Prologue: Q tile + tile 0 in one group.
#pragma unroll
  for (int i = 0; i < 16; i++) {
    int idx = tid + i * 256;
    int r = idx >> 5, c4 = idx & 31;
    cp_async16(sbase + (QS_OFF + r * AQ_STR + c4 * 4) * 4,
               Q + ((size_t)(b * NS + q0 + r)) * ND + h * NDH + c4 * 4);
  }
  load_tile(0);

  float oacc[16][4];
#pragma unroll
  for (int nf = 0; nf < 16; nf++)
#pragma unroll
    for (int r = 0; r < 4; r++) oacc[nf][r] = 0.f;
  float mrow0 = -1e30f, mrow1 = -1e30f;
  float lrow0 = 0.f, lrow1 = 0.f;

  const int r0 = w * 16 + gid;
  const int srcA = (lane & ~3) | (tg >> 1);
  const int srcB = (lane & ~3) | ((tg >> 1) + 2);

  for (int kt = 0; kt < nkt; kt++) {
    if (kt + 1 < nkt) {
      load_tile(kt + 1);
      cp_async_wait<1>();
    } else {
      cp_async_wait<0>();
    }
    __syncthreads();

    const uint32_t* ksb = smu + KS_OFF + (kt & 1) * KS_SZ;
    const uint32_t* vtb = smu + VT_OFF + (kt & 1) * VT_SZ;

    // ---- S = Q K^T (LDS.64 fragments; cols pre-interleaved) ----
    float sacc[8][4];
#pragma unroll
    for (int nf = 0; nf < 8; nf++)
#pragma unroll
      for (int r = 0; r < 4; r++) sacc[nf][r] = 0.f;

#pragma unroll
    for (int k8 = 0; k8 < 16; k8++) {
      uint32_t a[4];
      const uint32_t* ap = smu + QS_OFF + r0 * AQ_STR + k8 * 8 + 2 * tg;
      uint2 av0 = *(const uint2*)ap;
      uint2 av1 = *(const uint2*)(ap + 8 * AQ_STR);
      a[0] = av0.x;
      a[1] = av1.x;
      a[2] = av0.y;
      a[3] = av1.y;
#pragma unroll
      for (int nf = 0; nf < 8; nf++) {
        uint2 bv = *(const uint2*)(ksb + (nf * 8 + gid) * AQ_STR + k8 * 8 + 2 * tg);
        uint32_t bf[2] = {bv.x, bv.y};
        mma_tf32(sacc[nf], a, bf);
      }
    }

    // ---- scale + causal mask ----
    const bool partial = ((kt + 1) * 64 - 1) > (q0 + pl);
    if (partial) {
      const int L0 = q0 + pl + r0;
      const int L1 = L0 + 8;
      const int jb = kt * 64 + 2 * tg;
#pragma unroll
      for (int nf = 0; nf < 8; nf++) {
        int j0 = jb + nf * 8;
        sacc[nf][0] = (j0 <= L0) ? sacc[nf][0] * scale : -1e30f;
        sacc[nf][1] = (j0 + 1 <= L0) ? sacc[nf][1] * scale : -1e30f;
        sacc[nf][2] = (j0 <= L1) ? sacc[nf][2] * scale : -1e30f;
        sacc[nf][3] = (j0 + 1 <= L1) ? sacc[nf][3] * scale : -1e30f;
      }
    } else {
#pragma unroll
      for (int nf = 0; nf < 8; nf++)
#pragma unroll
        for (int r = 0; r < 4; r++) sacc[nf][r] *= scale;
    }

    // ---- online softmax ----
    float m0 = -1e30f, m1 = -1e30f;
#pragma unroll
    for (int nf = 0; nf < 8; nf++) {
      m0 = fmaxf(m0, fmaxf(sacc[nf][0], sacc[nf][1]));
      m1 = fmaxf(m1, fmaxf(sacc[nf][2], sacc[nf][3]));
    }
    m0 = fmaxf(m0, __shfl_xor_sync(0xffffffffu, m0, 1));
    m0 = fmaxf(m0, __shfl_xor_sync(0xffffffffu, m0, 2));
    m1 = fmaxf(m1, __shfl_xor_sync(0xffffffffu, m1, 1));
    m1 = fmaxf(m1, __shfl_xor_sync(0xffffffffu, m1, 2));

    const float mn0 = fmaxf(mrow0, m0);
    const float mn1 = fmaxf(mrow1, m1);
    const float al0 = __expf(mrow0 - mn0);
    const float al1 = __expf(mrow1 - mn1);
    mrow0 = mn0;
    mrow1 = mn1;

    uint32_t pc[8][4];
    float s0 = 0.f, s1 = 0.f;
#pragma unroll
    for (int nf = 0; nf < 8; nf++) {
      float p00 = __expf(sacc[nf][0] - mn0);
      float p01 = __expf(sacc[nf][1] - mn0);
      float p10 = __expf(sacc[nf][2] - mn1);
      float p11 = __expf(sacc[nf][3] - mn1);
      s0 += p00 + p01;
      s1 += p10 + p11;
      pc[nf][0] = f2tf32(p00);
      pc[nf][1] = f2tf32(p01);
      pc[nf][2] = f2tf32(p10);
      pc[nf][3] = f2tf32(p11);
    }
    s0 += __shfl_xor_sync(0xffffffffu, s0, 1);
    s0 += __shfl_xor_sync(0xffffffffu, s0, 2);
    s1 += __shfl_xor_sync(0xffffffffu, s1, 1);
    s1 += __shfl_xor_sync(0xffffffffu, s1, 2);
    lrow0 = lrow0 * al0 + s0;
    lrow1 = lrow1 * al1 + s1;

#pragma unroll
    for (int nf = 0; nf < 16; nf++) {
      oacc[nf][0] *= al0;
      oacc[nf][1] *= al0;
      oacc[nf][2] *= al1;
      oacc[nf][3] *= al1;
    }

    // ---- O += P V : P via intra-quad shuffles; V^T fragments via LDS.64 ----
#pragma unroll
    for (int k8 = 0; k8 < 8; k8++) {
      uint32_t t00 = __shfl_sync(0xffffffffu, pc[k8][0], srcA);
      uint32_t t01 = __shfl_sync(0xffffffffu, pc[k8][1], srcA);
      uint32_t t10 = __shfl_sync(0xffffffffu, pc[k8][2], srcA);
      uint32_t t11 = __shfl_sync(0xffffffffu, pc[k8][3], srcA);
      uint32_t u00 = __shfl_sync(0xffffffffu, pc[k8][0], srcB);
      uint32_t u01 = __shfl_sync(0xffffffffu, pc[k8][1], srcB);
      uint32_t u10 = __shfl_sync(0xffffffffu, pc[k8][2], srcB);
      uint32_t u11 = __shfl_sync(0xffffffffu, pc[k8][3], srcB);
      uint32_t a[4];
      a[0] = (tg & 1) ? t01 : t00;
      a[1] = (tg & 1) ? t11 : t10;
      a[2] = (tg & 1) ? u01 : u00;
      a[3] = (tg & 1) ? u11 : u10;
#pragma unroll
      for (int nf = 0; nf < 16; nf++) {
        uint2 bv = *(const uint2*)(vtb + (nf * 8 + gid) * AVT_STR + k8 * 8 + 2 * tg);
        uint32_t bf[2] = {bv.x, bv.y};
        mma_tf32(oacc[nf], a, bf);
      }
    }
    __syncthreads();
  }

  // ---- epilogue: normalize, tf32-round, write O col-interleaved ----
  const float inv0 = 1.0f / lrow0;
  const float inv1 = 1.0f / lrow1;
  const size_t grow0 = (size_t)(b * NS + q0 + r0) * ND + h * NDH;
  const size_t grow1 = grow0 + (size_t)8 * ND;
#pragma unroll
  for (int nf = 0; nf < 16; nf++) {
    int c0 = nf * 8 + 2 * tg;
    int m0c = colmap8(c0), m1c = colmap8(c0 + 1);
    O[grow0 + m0c] = f2tf32f(oacc[nf][0] * inv0);
    O[grow0 + m1c] = f2tf32f(oacc[nf][1] * inv0);
    O[grow1 + m0c] = f2tf32f(oacc[nf][2] * inv1);
    O[grow1 + m1c] = f2tf32f(oacc[nf][3] * inv1);
  }
}

// ---------------------------------------------------------------------------
extern "C" void kernel_launch(void* const* d_in, const int* in_sizes, int n_in,
                              void* d_out, int out_size) {
  const float* x   = (const float*)d_in[0];
  const float* wq  = (const float*)d_in[1];
  const float* wkv = (const float*)d_in[2];
  const float* wo  = (const float*)d_in[3];
  const int*  past = (const int*)d_in[4];

  float* out  = (float*)d_out;
  float* Kout = out + (size_t)NTOK * ND;
  float* Vout = Kout + (size_t)NTOK * NDH;

  float *Qs, *Os, *KVs, *Krs, *Vts, *xr, *wqr, *wor, *wkvT;
  cudaGetSymbolAddress((void**)&Qs, g_Q);
  cudaGetSymbolAddress((void**)&Os, g_O);
  cudaGetSymbolAddress((void**)&KVs, g_KV);
  cudaGetSymbolAddress((void**)&Krs, g_Kr);
  cudaGetSymbolAddress((void**)&Vts, g_Vt);
  cudaGetSymbolAddress((void**)&xr, g_xr);
  cudaGetSymbolAddress((void**)&wqr, g_wqr);
  cudaGetSymbolAddress((void**)&wor, g_wor);
  cudaGetSymbolAddress((void**)&wkvT, g_wkvT);

  cudaFuncSetAttribute(tf32_mma_gemm,
                       cudaFuncAttributeMaxDynamicSharedMemorySize, MMA_SMEM);
  cudaFuncSetAttribute(attn_mma_kernel,
                       cudaFuncAttributeMaxDynamicSharedMemorySize, ATTN_SMEM);

  // Pre-round operands to tf32 in gmem (wo also col-interleaved)
  round_tf32_kernel<<<(NTOK * ND / 4 + 255) / 256, 256>>>(x, xr, NTOK * ND / 4);
  round_tf32_kernel<<<(ND * ND / 4 + 255) / 256, 256>>>(wq, wqr, ND * ND / 4);
  round_tf32_ilv_kernel<<<(ND * ND / 4 + 255) / 256, 256>>>(wo, wor, ND * ND / 4);
  transpose_round_kernel<<<dim3(ND / 32, 256 / 32), dim3(32, 8)>>>(wkv, wkvT);

  // Q = x @ wq.T
  tf32_mma_gemm<<<dim3(ND / TBN, NTOK / TBM), 256, MMA_SMEM>>>(
      xr, wqr, Qs, NTOK, ND, ND);
  // KV = x @ wkv
  tf32_mma_gemm<<<dim3(256 / TBN, NTOK / TBM), 256, MMA_SMEM>>>(
      xr, wkvT, KVs, NTOK, 256, ND);
  // RoPE Q in place (tf32 + interleave)
  rope_q_kernel<<<NTOK, 1024>>>(Qs, past);
  // Split K/V to outputs; roped K scratch
  split_rope_k_kernel<<<NTOK, 128>>>(KVs, Kout, Vout, Krs);
  // V^T with interleaved key slots (for LDS.64 PV fragments)
  transpose_v_kernel<<<dim3(NTOK / 32, NDH / 32), dim3(32, 8)>>>(KVs, Vts);
  // Flash attention (tf32 tensor cores, pipelined, all-LDS.64 fragments)
  attn_mma_kernel<<<dim3(NS / 128, NH, NB), 256, ATTN_SMEM>>>(
      Qs, Krs, Vts, Os, past);
  // out = O @ wo.T (both sides col-interleaved in K)
  tf32_mma_gemm<<<dim3(ND / TBN, NTOK / TBM), 256, MMA_SMEM>>>(
      Os, wor, out, NTOK, ND, ND);
}

// round 10
// speedup vs baseline: 1.0023x; 1.0023x over previous
#include <cuda_runtime.h>
#include <cstdint>

#define NB   2
#define NS   2048
#define ND   2048
#define NH   16
#define NDH  128
#define NTOK (NB * NS)

// Scratch (device globals: no allocation allowed in kernel_launch)
__device__ float g_Q  [(size_t)NTOK * ND];      // roped Q (tf32, col-interleaved)
__device__ float g_O  [(size_t)NTOK * ND];      // attention out (tf32, col-interleaved)
__device__ float g_KV [(size_t)NTOK * 2 * NDH]; // KV projection result
__device__ float g_Kr [(size_t)NTOK * NDH];     // roped K (tf32, col-interleaved)
__device__ float g_Vt [(size_t)NDH * NTOK];     // V^T (tf32), key dim pair-interleaved
__device__ float g_xr [(size_t)NTOK * ND];      // x  (tf32, plain)
__device__ float g_wqr[(size_t)ND * ND];        // wq (tf32, plain)
__device__ float g_wor[(size_t)ND * ND];        // wo (tf32, col-interleaved)
__device__ float g_wkvT[(size_t)256 * ND];      // wkv^T (tf32, plain)

// ===========================================================================
// Helpers
// ===========================================================================
__device__ __forceinline__ uint32_t smem_u32(const void* p) {
  uint32_t a;
  asm("{ .reg .u64 t; cvta.to.shared.u64 t, %1; cvt.u32.u64 %0, t; }"
      : "=r"(a) : "l"(p));
  return a;
}
__device__ __forceinline__ void cp_async16(uint32_t dst, const void* src) {
  asm volatile("cp.async.cg.shared.global [%0], [%1], 16;" ::"r"(dst), "l"(src));
}
#define CP_ASYNC_COMMIT() asm volatile("cp.async.commit_group;" ::: "memory")
template <int N>
__device__ __forceinline__ void cp_async_wait() {
  asm volatile("cp.async.wait_group %0;" ::"n"(N) : "memory");
}
__device__ __forceinline__ uint32_t f2tf32(float x) {
  uint32_t r;
  asm("cvt.rna.tf32.f32 %0, %1;" : "=r"(r) : "f"(x));
  return r;
}
__device__ __forceinline__ float f2tf32f(float x) {
  return __uint_as_float(f2tf32(x));
}
__device__ __forceinline__ void mma_tf32(float* c, const uint32_t* a,
                                         const uint32_t* b) {
  asm volatile(
      "mma.sync.aligned.m16n8k8.row.col.f32.tf32.tf32.f32 "
      "{%0,%1,%2,%3}, {%4,%5,%6,%7}, {%8,%9}, {%0,%1,%2,%3};"
      : "+f"(c[0]), "+f"(c[1]), "+f"(c[2]), "+f"(c[3])
      : "r"(a[0]), "r"(a[1]), "r"(a[2]), "r"(a[3]), "r"(b[0]), "r"(b[1]));
}
// Pair interleave within each 8-group: fragment pair (c, c+4) -> adjacent.
__device__ __forceinline__ int colmap8(int c) {
  int r = c & 7;
  return (c & ~7) | ((r < 4) ? (r << 1) : (((r - 4) << 1) | 1));
}
// Inverse: word slot w -> original index.
__device__ __forceinline__ int invmap8(int w) {
  int r = w & 7;
  return (w & ~7) | ((r & 1) ? ((r >> 1) + 4) : (r >> 1));
}

// ===========================================================================
// tf32 mma.sync GEMM: C[M,N] = A[M,K] @ B[N,K]^T. Operands PRE-ROUNDED tf32.
// Tile 128x128x32, 256 threads, 3 stages, single barrier per chunk.
// ===========================================================================
#define TBM 128
#define TBN 128
#define TBK 32
#define TSTRIDE 36
#define TILE_FLOATS (TBM * TSTRIDE)
#define STAGE_FLOATS (2 * TILE_FLOATS)
#define TSTAGES 3
#define MMA_SMEM (TSTAGES * STAGE_FLOATS * 4)

__global__ void __launch_bounds__(256, 2)
tf32_mma_gemm(const float* __restrict__ A, const float* __restrict__ B,
              float* __restrict__ C, int M, int N, int K) {
  extern __shared__ float sm[];
  const uint32_t* smu = (const uint32_t*)sm;
  const int tid = threadIdx.x;
  const int wid = tid >> 5;
  const int lane = tid & 31;
  const int gid = lane >> 2;
  const int tg = lane & 3;
  const int wm = wid & 1;
  const int wn = wid >> 1;
  const int bm = blockIdx.y * TBM;
  const int bn = blockIdx.x * TBN;
  const int nchunks = K / TBK;

  const float* gA = A + (size_t)bm * K;
  const float* gB = B + (size_t)bn * K;
  const uint32_t sbase = smem_u32(sm);

  auto load_chunk = [&](int c) {
    const int s = c % TSTAGES;
    const uint32_t sa = sbase + s * STAGE_FLOATS * 4;
    const uint32_t sbb = sa + TILE_FLOATS * 4;
    const int k0 = c * TBK;
#pragma unroll
    for (int i = 0; i < 4; i++) {
      int idx = tid + i * 256;
      int r = idx >> 3, c4 = idx & 7;
      cp_async16(sa + (r * TSTRIDE + c4 * 4) * 4, gA + (size_t)r * K + k0 + c4 * 4);
    }
#pragma unroll
    for (int i = 0; i < 4; i++) {
      int idx = tid + i * 256;
      int r = idx >> 3, c4 = idx & 7;
      cp_async16(sbb + (r * TSTRIDE + c4 * 4) * 4, gB + (size_t)r * K + k0 + c4 * 4);
    }
    CP_ASYNC_COMMIT();
  };

  float acc[4][4][4];
#pragma unroll
  for (int mf = 0; mf < 4; mf++)
#pragma unroll
    for (int nf = 0; nf < 4; nf++)
#pragma unroll
      for (int r = 0; r < 4; r++) acc[mf][nf][r] = 0.f;

  load_chunk(0);
  load_chunk(1);

  for (int i = 0; i < nchunks; i++) {
    if (i < nchunks - 1)
      cp_async_wait<1>();
    else
      cp_async_wait<0>();
    __syncthreads();
    // Single barrier per chunk: stage (i+2)%3's previous readers (iter i-1)
    // are guaranteed past by the sync above.
    if (i + 2 < nchunks) load_chunk(i + 2);

    const uint32_t* As = smu + (i % TSTAGES) * STAGE_FLOATS;
    const uint32_t* Bs = As + TILE_FLOATS;

#pragma unroll
    for (int k8 = 0; k8 < 4; k8++) {
      uint32_t a[4][4], b[4][2];
#pragma unroll
      for (int mf = 0; mf < 4; mf++) {
        const uint32_t* ap = As + (wm * 64 + mf * 16 + gid) * TSTRIDE + k8 * 8 + tg;
        a[mf][0] = ap[0];
        a[mf][1] = ap[8 * TSTRIDE];
        a[mf][2] = ap[4];
        a[mf][3] = ap[8 * TSTRIDE + 4];
      }
#pragma unroll
      for (int nf = 0; nf < 4; nf++) {
        const uint32_t* bp = Bs + (wn * 32 + nf * 8 + gid) * TSTRIDE + k8 * 8 + tg;
        b[nf][0] = bp[0];
        b[nf][1] = bp[4];
      }
#pragma unroll
      for (int mf = 0; mf < 4; mf++)
#pragma unroll
        for (int nf = 0; nf < 4; nf++) mma_tf32(acc[mf][nf], a[mf], b[nf]);
    }
  }

#pragma unroll
  for (int mf = 0; mf < 4; mf++) {
    int row0 = bm + wm * 64 + mf * 16 + gid;
#pragma unroll
    for (int nf = 0; nf < 4; nf++) {
      int col = bn + wn * 32 + nf * 8 + 2 * tg;
      *(float2*)(C + (size_t)row0 * N + col) =
          make_float2(acc[mf][nf][0], acc[mf][nf][1]);
      *(float2*)(C + (size_t)(row0 + 8) * N + col) =
          make_float2(acc[mf][nf][2], acc[mf][nf][3]);
    }
  }
}

// ---------------------------------------------------------------------------
// Elementwise tf32 rounding; interleaved variant for wo.
// ---------------------------------------------------------------------------
__global__ void round_tf32_kernel(const float* __restrict__ in,
                                  float* __restrict__ out, int n4) {
  int i = blockIdx.x * 256 + threadIdx.x;
  if (i < n4) {
    float4 v = ((const float4*)in)[i];
    v.x = f2tf32f(v.x);
    v.y = f2tf32f(v.y);
    v.z = f2tf32f(v.z);
    v.w = f2tf32f(v.w);
    ((float4*)out)[i] = v;
  }
}

__global__ void round_tf32_ilv_kernel(const float* __restrict__ in,
                                      float* __restrict__ out, int n4) {
  int i = blockIdx.x * 256 + threadIdx.x;
  if (i < n4) {
    float4 v = ((const float4*)in)[i];
    int c = i * 4;
    out[colmap8(c + 0)] = f2tf32f(v.x);
    out[colmap8(c + 1)] = f2tf32f(v.y);
    out[colmap8(c + 2)] = f2tf32f(v.z);
    out[colmap8(c + 3)] = f2tf32f(v.w);
  }
}

// ---------------------------------------------------------------------------
// Transpose + round: wkv [2048][256] -> wkvT [256][2048] (tf32).
// ---------------------------------------------------------------------------
__global__ void transpose_round_kernel(const float* __restrict__ in,
                                       float* __restrict__ out) {
  __shared__ float t[32][33];
  const int k0 = blockIdx.x * 32;
  const int n0 = blockIdx.y * 32;
  const int tx = threadIdx.x;
  const int ty = threadIdx.y;
#pragma unroll
  for (int j = 0; j < 4; j++)
    t[ty + 8 * j][tx] = in[(size_t)(k0 + ty + 8 * j) * 256 + n0 + tx];
  __syncthreads();
#pragma unroll
  for (int j = 0; j < 4; j++)
    out[(size_t)(n0 + ty + 8 * j) * 2048 + k0 + tx] = f2tf32f(t[tx][ty + 8 * j]);
}

// ---------------------------------------------------------------------------
// V transpose: g_KV[tok][128+d] -> g_Vt[d][keyslot], keys pair-interleaved
// within 8-groups (key s stored at word colmap8(s)), tf32-rounded.
// ---------------------------------------------------------------------------
__global__ void transpose_v_kernel(const float* __restrict__ KV,
                                   float* __restrict__ Vt) {
  __shared__ float t[32][33];
  const int tok0 = blockIdx.x * 32;
  const int d0 = blockIdx.y * 32;
  const int tx = threadIdx.x;
  const int ty = threadIdx.y;
#pragma unroll
  for (int j = 0; j < 4; j++)
    t[ty + 8 * j][tx] = KV[(size_t)(tok0 + ty + 8 * j) * 256 + 128 + d0 + tx];
  __syncthreads();
#pragma unroll
  for (int j = 0; j < 4; j++) {
    int s = invmap8(tx);  // word slot tx holds key invmap8(tx)
    Vt[(size_t)(d0 + ty + 8 * j) * NTOK + tok0 + tx] = f2tf32f(t[s][ty + 8 * j]);
  }
}

// ---------------------------------------------------------------------------
// RoPE on Q, in-place, tf32-rounded + col-interleaved (per head).
// ---------------------------------------------------------------------------
__global__ void rope_q_kernel(float* __restrict__ Q, const int* __restrict__ past) {
  const int tok = blockIdx.x;
  const int s = tok % NS;
  const int pos = past[0] + s;
  const int t = threadIdx.x;
  const int h = t >> 6;
  const int i = t & 63;
  float fr = 1.0f / powf(10000.0f, (float)(2 * i) / 128.0f);
  float ang = (float)pos * fr;
  float sn, cs;
  sincosf(ang, &sn, &cs);
  float* q = Q + (size_t)tok * ND + h * NDH;
  float x1 = q[i];
  float x2 = q[i + 64];
  __syncthreads();  // in-place permuted writes: all reads first
  int ci = colmap8(i);
  q[ci]      = f2tf32f(x1 * cs - x2 * sn);
  q[ci + 64] = f2tf32f(x2 * cs + x1 * sn);
}

// ---------------------------------------------------------------------------
// Split KV: exact K/V outputs; Kr (roped, tf32, interleaved).
// ---------------------------------------------------------------------------
__global__ void split_rope_k_kernel(const float* __restrict__ KV,
                                    float* __restrict__ Kout,
                                    float* __restrict__ Vout,
                                    float* __restrict__ Kr) {
  const int tok = blockIdx.x;
  const int s = tok % NS;
  const int t = threadIdx.x;
  const float* kv = KV + (size_t)tok * 256;
  Kout[(size_t)tok * NDH + t] = kv[t];
  Vout[(size_t)tok * NDH + t] = kv[128 + t];
  if (t < 64) {
    float fr = 1.0f / powf(10000.0f, (float)(2 * t) / 128.0f);
    float ang = (float)s * fr;
    float sn, cs;
    sincosf(ang, &sn, &cs);
    float x1 = kv[t];
    float x2 = kv[t + 64];
    int ct = colmap8(t);
    Kr[(size_t)tok * NDH + ct]      = f2tf32f(x1 * cs - x2 * sn);
    Kr[(size_t)tok * NDH + ct + 64] = f2tf32f(x2 * cs + x1 * sn);
  }
}

// ===========================================================================
// Tensor-core flash attention, tf32 mma.sync, pipelined K/V double buffer.
// Q/K col-interleaved and V^T key-interleaved -> all fragment loads LDS.64.
// Smem (words): qs[128][136] | ks[2][64][136] | vt[2][128][72]
// ===========================================================================
#define AQ_STR 136
#define AVT_STR 72
#define QS_OFF 0
#define KS_OFF (128 * AQ_STR)                    // 17408
#define KS_SZ (64 * AQ_STR)                      // 8704
#define VT_OFF (KS_OFF + 2 * KS_SZ)              // 34816
#define VT_SZ (128 * AVT_STR)                    // 9216
#define ATTN_SMEM ((VT_OFF + 2 * VT_SZ) * 4)     // 212992 bytes

__global__ void __launch_bounds__(256, 1) attn_mma_kernel(
    const float* __restrict__ Q, const float* __restrict__ Kr,
    const float* __restrict__ Vt, float* __restrict__ O,
    const int* __restrict__ past) {
  extern __shared__ float sm[];
  uint32_t* smu = (uint32_t*)sm;
  const uint32_t sbase = smem_u32(sm);

  const int qt = (int)gridDim.x - 1 - (int)blockIdx.x;  // heavy tiles first
  const int h = blockIdx.y;
  const int b = blockIdx.z;
  const int tid = threadIdx.x;
  const int w = tid >> 5;
  const int lane = tid & 31;
  const int gid = lane >> 2;
  const int tg = lane & 3;
  const int q0 = qt * 128;
  const int pl = past[0];
  const float scale = 0.08838834764831845f;  // 1/sqrt(128)
  const int nkt = 2 * qt + 2;

  auto load_tile = [&](int kt) {
    const int s = kt & 1;
    const uint32_t ksb = sbase + (KS_OFF + s * KS_SZ) * 4;
    const uint32_t vtb = sbase + (VT_OFF + s * VT_SZ) * 4;
    const size_t tok0 = (size_t)(b * NS) + kt * 64;
#pragma unroll
    for (int i = 0; i < 8; i++) {
      int idx = tid + i * 256;
      int r = idx >> 5, c4 = idx & 31;
      cp_async16(ksb + (r * AQ_STR + c4 * 4) * 4, Kr + (tok0 + r) * NDH + c4 * 4);
    }
    // V^T tile: 128 dh-rows x 64 keys (key slots pre-interleaved in gmem)
#pragma unroll
    for (int i = 0; i < 8; i++) {
      int idx = tid + i * 256;
      int r = idx >> 4, c4 = idx & 15;  // dh row r, 16B chunk c4
      cp_async16(vtb + (r * AVT_STR + c4 * 4) * 4,
                 Vt + (size_t)r * NTOK + tok0 + c4 * 4);
    }
    CP_ASYNC_COMMIT();
  };

  // Prologue: Q tile + tile 0 in one group.
#pragma unroll
  for (int i = 0; i < 16; i++) {
    int idx = tid + i * 256;
    int r = idx >> 5, c4 = idx & 31;
    cp_async16(sbase + (QS_OFF + r * AQ_STR + c4 * 4) * 4,
               Q + ((size_t)(b * NS + q0 + r)) * ND + h * NDH + c4 * 4);
  }
  load_tile(0);

  float oacc[16][4];
#pragma unroll
  for (int nf = 0; nf < 16; nf++)
#pragma unroll
    for (int r = 0; r < 4; r++) oacc[nf][r] = 0.f;
  float mrow0 = -1e30f, mrow1 = -1e30f;
  float lrow0 = 0.f, lrow1 = 0.f;

  const int r0 = w * 16 + gid;
  const int srcA = (lane & ~3) | (tg >> 1);
  const int srcB = (lane & ~3) | ((tg >> 1) + 2);

  for (int kt = 0; kt < nkt; kt++) {
    if (kt + 1 < nkt) {
      load_tile(kt + 1);
      cp_async_wait<1>();
    } else {
      cp_async_wait<0>();
    }
    __syncthreads();

    const uint32_t* ksb = smu + KS_OFF + (kt & 1) * KS_SZ;
    const uint32_t* vtb = smu + VT_OFF + (kt & 1) * VT_SZ;

    // ---- S = Q K^T (LDS.64 fragments; cols pre-interleaved) ----
    float sacc[8][4];
#pragma unroll
    for (int nf = 0; nf < 8; nf++)
#pragma unroll
      for (int r = 0; r < 4; r++) sacc[nf][r] = 0.f;

#pragma unroll
    for (int k8 = 0; k8 < 16; k8++) {
      uint32_t a[4];
      const uint32_t* ap = smu + QS_OFF + r0 * AQ_STR + k8 * 8 + 2 * tg;
      uint2 av0 = *(const uint2*)ap;
      uint2 av1 = *(const uint2*)(ap + 8 * AQ_STR);
      a[0] = av0.x;
      a[1] = av1.x;
      a[2] = av0.y;
      a[3] = av1.y;
#pragma unroll
      for (int nf = 0; nf < 8; nf++) {
        uint2 bv = *(const uint2*)(ksb + (nf * 8 + gid) * AQ_STR + k8 * 8 + 2 * tg);
        uint32_t bf[2] = {bv.x, bv.y};
        mma_tf32(sacc[nf], a, bf);
      }
    }

    // ---- scale + causal mask ----
    const bool partial = ((kt + 1) * 64 - 1) > (q0 + pl);
    if (partial) {
      const int L0 = q0 + pl + r0;
      const int L1 = L0 + 8;
      const int jb = kt * 64 + 2 * tg;
#pragma unroll
      for (int nf = 0; nf < 8; nf++) {
        int j0 = jb + nf * 8;
        sacc[nf][0] = (j0 <= L0) ? sacc[nf][0] * scale : -1e30f;
        sacc[nf][1] = (j0 + 1 <= L0) ? sacc[nf][1] * scale : -1e30f;
        sacc[nf][2] = (j0 <= L1) ? sacc[nf][2] * scale : -1e30f;
        sacc[nf][3] = (j0 + 1 <= L1) ? sacc[nf][3] * scale : -1e30f;
      }
    } else {
#pragma unroll
      for (int nf = 0; nf < 8; nf++)
#pragma unroll
        for (int r = 0; r < 4; r++) sacc[nf][r] *= scale;
    }

    // ---- online softmax ----
    float m0 = -1e30f, m1 = -1e30f;
#pragma unroll
    for (int nf = 0; nf < 8; nf++) {
      m0 = fmaxf(m0, fmaxf(sacc[nf][0], sacc[nf][1]));
      m1 = fmaxf(m1, fmaxf(sacc[nf][2], sacc[nf][3]));
    }
    m0 = fmaxf(m0, __shfl_xor_sync(0xffffffffu, m0, 1));
    m0 = fmaxf(m0, __shfl_xor_sync(0xffffffffu, m0, 2));
    m1 = fmaxf(m1, __shfl_xor_sync(0xffffffffu, m1, 1));
    m1 = fmaxf(m1, __shfl_xor_sync(0xffffffffu, m1, 2));

    const float mn0 = fmaxf(mrow0, m0);
    const float mn1 = fmaxf(mrow1, m1);
    const float al0 = __expf(mrow0 - mn0);
    const float al1 = __expf(mrow1 - mn1);
    mrow0 = mn0;
    mrow1 = mn1;

    uint32_t pc[8][4];
    float s0 = 0.f, s1 = 0.f;
#pragma unroll
    for (int nf = 0; nf < 8; nf++) {
      float p00 = __expf(sacc[nf][0] - mn0);
      float p01 = __expf(sacc[nf][1] - mn0);
      float p10 = __expf(sacc[nf][2] - mn1);
      float p11 = __expf(sacc[nf][3] - mn1);
      s0 += p00 + p01;
      s1 += p10 + p11;
      pc[nf][0] = f2tf32(p00);
      pc[nf][1] = f2tf32(p01);
      pc[nf][2] = f2tf32(p10);
      pc[nf][3] = f2tf32(p11);
    }
    s0 += __shfl_xor_sync(0xffffffffu, s0, 1);
    s0 += __shfl_xor_sync(0xffffffffu, s0, 2);
    s1 += __shfl_xor_sync(0xffffffffu, s1, 1);
    s1 += __shfl_xor_sync(0xffffffffu, s1, 2);
    lrow0 = lrow0 * al0 + s0;
    lrow1 = lrow1 * al1 + s1;

#pragma unroll
    for (int nf = 0; nf < 16; nf++) {
      oacc[nf][0] *= al0;
      oacc[nf][1] *= al0;
      oacc[nf][2] *= al1;
      oacc[nf][3] *= al1;
    }

    // ---- O += P V : P via intra-quad shuffles; V^T fragments via LDS.64 ----
#pragma unroll
    for (int k8 = 0; k8 < 8; k8++) {
      uint32_t t00 = __shfl_sync(0xffffffffu, pc[k8][0], srcA);
      uint32_t t01 = __shfl_sync(0xffffffffu, pc[k8][1], srcA);
      uint32_t t10 = __shfl_sync(0xffffffffu, pc[k8][2], srcA);
      uint32_t t11 = __shfl_sync(0xffffffffu, pc[k8][3], srcA);
      uint32_t u00 = __shfl_sync(0xffffffffu, pc[k8][0], srcB);
      uint32_t u01 = __shfl_sync(0xffffffffu, pc[k8][1], srcB);
      uint32_t u10 = __shfl_sync(0xffffffffu, pc[k8][2], srcB);
      uint32_t u11 = __shfl_sync(0xffffffffu, pc[k8][3], srcB);
      uint32_t a[4];
      a[0] = (tg & 1) ? t01 : t00;
      a[1] = (tg & 1) ? t11 : t10;
      a[2] = (tg & 1) ? u01 : u00;
      a[3] = (tg & 1) ? u11 : u10;
#pragma unroll
      for (int nf = 0; nf < 16; nf++) {
        uint2 bv = *(const uint2*)(vtb + (nf * 8 + gid) * AVT_STR + k8 * 8 + 2 * tg);
        uint32_t bf[2] = {bv.x, bv.y};
        mma_tf32(oacc[nf], a, bf);
      }
    }
    __syncthreads();
  }

  // ---- epilogue: normalize, tf32-round, write O col-interleaved ----
  const float inv0 = 1.0f / lrow0;
  const float inv1 = 1.0f / lrow1;
  const size_t grow0 = (size_t)(b * NS + q0 + r0) * ND + h * NDH;
  const size_t grow1 = grow0 + (size_t)8 * ND;
#pragma unroll
  for (int nf = 0; nf < 16; nf++) {
    int c0 = nf * 8 + 2 * tg;
    int m0c = colmap8(c0), m1c = colmap8(c0 + 1);
    O[grow0 + m0c] = f2tf32f(oacc[nf][0] * inv0);
    O[grow0 + m1c] = f2tf32f(oacc[nf][1] * inv0);
    O[grow1 + m0c] = f2tf32f(oacc[nf][2] * inv1);
    O[grow1 + m1c] = f2tf32f(oacc[nf][3] * inv1);
  }
}

// ---------------------------------------------------------------------------
extern "C" void kernel_launch(void* const* d_in, const int* in_sizes, int n_in,
                              void* d_out, int out_size) {
  const float* x   = (const float*)d_in[0];
  const float* wq  = (const float*)d_in[1];
  const float* wkv = (const float*)d_in[2];
  const float* wo  = (const float*)d_in[3];
  const int*  past = (const int*)d_in[4];

  float* out  = (float*)d_out;
  float* Kout = out + (size_t)NTOK * ND;
  float* Vout = Kout + (size_t)NTOK * NDH;

  float *Qs, *Os, *KVs, *Krs, *Vts, *xr, *wqr, *wor, *wkvT;
  cudaGetSymbolAddress((void**)&Qs, g_Q);
  cudaGetSymbolAddress((void**)&Os, g_O);
  cudaGetSymbolAddress((void**)&KVs, g_KV);
  cudaGetSymbolAddress((void**)&Krs, g_Kr);
  cudaGetSymbolAddress((void**)&Vts, g_Vt);
  cudaGetSymbolAddress((void**)&xr, g_xr);
  cudaGetSymbolAddress((void**)&wqr, g_wqr);
  cudaGetSymbolAddress((void**)&wor, g_wor);
  cudaGetSymbolAddress((void**)&wkvT, g_wkvT);

  cudaFuncSetAttribute(tf32_mma_gemm,
                       cudaFuncAttributeMaxDynamicSharedMemorySize, MMA_SMEM);
  cudaFuncSetAttribute(attn_mma_kernel,
                       cudaFuncAttributeMaxDynamicSharedMemorySize, ATTN_SMEM);

  // Pre-round operands to tf32 in gmem (wo also col-interleaved)
  round_tf32_kernel<<<(NTOK * ND / 4 + 255) / 256, 256>>>(x, xr, NTOK * ND / 4);
  round_tf32_kernel<<<(ND * ND / 4 + 255) / 256, 256>>>(wq, wqr, ND * ND / 4);
  round_tf32_ilv_kernel<<<(ND * ND / 4 + 255) / 256, 256>>>(wo, wor, ND * ND / 4);
  transpose_round_kernel<<<dim3(ND / 32, 256 / 32), dim3(32, 8)>>>(wkv, wkvT);

  // Q = x @ wq.T
  tf32_mma_gemm<<<dim3(ND / TBN, NTOK / TBM), 256, MMA_SMEM>>>(
      xr, wqr, Qs, NTOK, ND, ND);
  // KV = x @ wkv
  tf32_mma_gemm<<<dim3(256 / TBN, NTOK / TBM), 256, MMA_SMEM>>>(
      xr, wkvT, KVs, NTOK, 256, ND);
  // RoPE Q in place (tf32 + interleave)
  rope_q_kernel<<<NTOK, 1024>>>(Qs, past);
  // Split K/V to outputs; roped K scratch
  split_rope_k_kernel<<<NTOK, 128>>>(KVs, Kout, Vout, Krs);
  // V^T with interleaved key slots (for LDS.64 PV fragments)
  transpose_v_kernel<<<dim3(NTOK / 32, NDH / 32), dim3(32, 8)>>>(KVs, Vts);
  // Flash attention (tf32 tensor cores, pipelined, all-LDS.64 fragments)
  attn_mma_kernel<<<dim3(NS / 128, NH, NB), 256, ATTN_SMEM>>>(
      Qs, Krs, Vts, Os, past);
  // out = O @ wo.T (both sides col-interleaved in K)
  tf32_mma_gemm<<<dim3(ND / TBN, NTOK / TBM), 256, MMA_SMEM>>>(
      Os, wor, out, NTOK, ND, ND);
}